// round 5
// baseline (speedup 1.0000x reference)
#include <cuda_runtime.h>
#include <cuda_bf16.h>
#include <mma.h>
#include <math.h>
#include <stdint.h>

using namespace nvcuda;

// Problem constants
#define BATCH 2
#define T 2048
#define DIM 2048
#define NHEAD 16
#define HDIM 128
#define INNER 2048           // NHEAD * HDIM
#define BT 4096              // BATCH * T
#define K3 6144              // 3 * INNER

// ---------------- scratch (device globals; no allocation allowed) ----------------
__device__ float g_qkv[(size_t)BT * K3];        // 96 MB fp32 qkv
__device__ float g_attn[(size_t)BT * INNER];    // 32 MB fp32 attention out
__device__ float g_cos[T * 64];
__device__ float g_sin[T * 64];
// bf16 split buffers
__device__ __nv_bfloat16 g_x_hi[(size_t)BT * DIM];
__device__ __nv_bfloat16 g_x_lo[(size_t)BT * DIM];
__device__ __nv_bfloat16 g_wqkvT_hi[(size_t)K3 * DIM];    // [N=6144][K=2048]
__device__ __nv_bfloat16 g_wqkvT_lo[(size_t)K3 * DIM];
__device__ __nv_bfloat16 g_woutT_hi[(size_t)DIM * INNER]; // [N=2048][K=2048]
__device__ __nv_bfloat16 g_woutT_lo[(size_t)DIM * INNER];
__device__ __nv_bfloat16 g_attn_hi[(size_t)BT * INNER];
__device__ __nv_bfloat16 g_attn_lo[(size_t)BT * INNER];

// ---------------- arch-generic PTX helpers (sm_80+ ISA only) ----------------
__device__ __forceinline__ uint32_t smem_u32(const void* p) {
    uint32_t a;
    asm("{ .reg .u64 t; cvta.to.shared.u64 t, %1; cvt.u32.u64 %0, t; }" : "=r"(a) : "l"(p));
    return a;
}
__device__ __forceinline__ void cp_async16(uint32_t dst, const void* src) {
    asm volatile("cp.async.cg.shared.global [%0], [%1], 16;\n"
                 :: "r"(dst), "l"(__cvta_generic_to_global(src)) : "memory");
}
__device__ __forceinline__ void cp_commit() {
    asm volatile("cp.async.commit_group;\n" ::: "memory");
}
template <int N>
__device__ __forceinline__ void cp_wait() {
    asm volatile("cp.async.wait_group %0;\n" :: "n"(N) : "memory");
}

// ================= RoPE tables =================
__global__ void build_rope_tables() {
    int idx = blockIdx.x * blockDim.x + threadIdx.x;
    if (idx >= T * 64) return;
    int j = idx & 63;
    int t = idx >> 6;
    double invf = exp(-(double)j * 0.015625 * 9.210340371976182736);   // 10000^(-j/64)
    float angle = (float)t * (float)invf;   // fp32 product matches reference rounding
    g_cos[idx] = (float)cos((double)angle);
    g_sin[idx] = (float)sin((double)angle);
}

// ================= in-place RoPE on q and k =================
__global__ __launch_bounds__(256) void rope_kernel(float* __restrict__ qkv) {
    int idx = blockIdx.x * blockDim.x + threadIdx.x;
    if (idx >= BT * NHEAD * 64) return;
    int j   = idx & 63;
    int h   = (idx >> 6) & 15;
    int row = idx >> 10;
    int t   = row & (T - 1);
    float c = g_cos[t * 64 + j];
    float s = g_sin[t * 64 + j];
    float* base = qkv + (size_t)row * K3 + h * HDIM;
    float a = base[j], b = base[j + 64];
    base[j]      = a * c - b * s;
    base[j + 64] = b * c + a * s;
    float* kb = base + INNER;
    a = kb[j]; b = kb[j + 64];
    kb[j]      = a * c - b * s;
    kb[j + 64] = b * c + a * s;
}

// ================= fp32 -> bf16 hi/lo split =================
__device__ __forceinline__ void split1(float v, __nv_bfloat16& h, __nv_bfloat16& l) {
    h = __float2bfloat16(v);
    l = __float2bfloat16(v - __bfloat162float(h));
}

__global__ __launch_bounds__(256) void split_rows_kernel(const float* __restrict__ in,
                                                         __nv_bfloat16* __restrict__ hi,
                                                         __nv_bfloat16* __restrict__ lo, int n4) {
    int i = blockIdx.x * blockDim.x + threadIdx.x;
    if (i >= n4) return;
    float4 v = *(const float4*)(in + (size_t)i * 4);
    __nv_bfloat16 h0, l0, h1, l1, h2, l2, h3, l3;
    split1(v.x, h0, l0); split1(v.y, h1, l1); split1(v.z, h2, l2); split1(v.w, h3, l3);
    __nv_bfloat162* hp = (__nv_bfloat162*)(hi + (size_t)i * 4);
    __nv_bfloat162* lp = (__nv_bfloat162*)(lo + (size_t)i * 4);
    hp[0] = __nv_bfloat162(h0, h1); hp[1] = __nv_bfloat162(h2, h3);
    lp[0] = __nv_bfloat162(l0, l1); lp[1] = __nv_bfloat162(l2, l3);
}

// transpose + split: in [K][N] fp32 -> hiT/loT [N][K] bf16
__global__ void split_transpose_kernel(const float* __restrict__ in,
                                       __nv_bfloat16* __restrict__ hiT,
                                       __nv_bfloat16* __restrict__ loT, int K, int N) {
    __shared__ float t[32][33];
    int n0 = blockIdx.x * 32, k0 = blockIdx.y * 32;
    int tx = threadIdx.x, ty = threadIdx.y;   // block (32, 8)
#pragma unroll
    for (int i = 0; i < 32; i += 8)
        t[ty + i][tx] = in[(size_t)(k0 + ty + i) * N + n0 + tx];
    __syncthreads();
#pragma unroll
    for (int i = 0; i < 32; i += 8) {
        float v = t[tx][ty + i];
        __nv_bfloat16 h, l;
        split1(v, h, l);
        size_t o = (size_t)(n0 + ty + i) * K + k0 + tx;
        hiT[o] = h;
        loT[o] = l;
    }
}

// ================= wmma split-bf16 GEMM =================
// C[M,N] = A[M,K] @ B[K,N], with B supplied transposed BT [N][K].
// CTA 128x128, 8 warps (2x4), warp tile 64x32 (4x2 wmma 16x16x16 tiles).
// Split products per k-step: Ah*Bh + Ah*Bl + Al*Bh (fp32 accum).
// cp.async double-buffered smem, tiles [128][40] bf16 (80B row stride: conflict-free ldmatrix).
#define GTILE 40                         // padded bf16 stride
#define ARR_BYTES (128 * GTILE * 2)      // 10240 B per tile
#define STAGE_BYTES (4 * ARR_BYTES)      // Ah, Al, Bh, Bl
#define GEMM_SMEM (2 * STAGE_BYTES)      // 81920 B

__global__ __launch_bounds__(256, 1) void gemm_bf16split(
    int M, int N, int K,
    const __nv_bfloat16* __restrict__ Ah, const __nv_bfloat16* __restrict__ Al,
    const __nv_bfloat16* __restrict__ BTh, const __nv_bfloat16* __restrict__ BTl,
    float* __restrict__ C) {
    extern __shared__ char sb[];
    uint32_t sb_u = smem_u32(sb);

    int tid = threadIdx.x;
    int wid = tid >> 5;
    int wm = wid >> 2;            // 0..1
    int wn = wid & 3;             // 0..3

    int m0 = blockIdx.y * 128;
    int n0 = blockIdx.x * 128;

    // per-thread load slots: 2 chunks per array per stage
    // idx = tid + c*256 in [0,512): row = idx>>2 (0..127), ch = idx&3 (16B chunk)
    const __nv_bfloat16* srcs[4] = {Ah, Al, BTh, BTl};
    int rbase[2], cbase[2];
#pragma unroll
    for (int c = 0; c < 2; c++) {
        int idx = tid + c * 256;
        rbase[c] = idx >> 2;
        cbase[c] = (idx & 3) * 8;   // bf16 offset within 32-wide chunk row
    }

    int KIT = K >> 5;   // 32 bf16 per chunk

    // issue stage 0
    {
        int k0 = 0;
#pragma unroll
        for (int a = 0; a < 4; a++) {
            const __nv_bfloat16* base = srcs[a];
            int row0 = (a < 2) ? m0 : n0;
#pragma unroll
            for (int c = 0; c < 2; c++) {
                uint32_t d = sb_u + a * ARR_BYTES + (rbase[c] * GTILE + cbase[c]) * 2;
                cp_async16(d, base + (size_t)(row0 + rbase[c]) * K + k0 + cbase[c]);
            }
        }
        cp_commit();
    }

    wmma::fragment<wmma::accumulator, 16, 16, 16, float> acc[4][2];
#pragma unroll
    for (int i = 0; i < 4; i++)
#pragma unroll
        for (int j = 0; j < 2; j++) wmma::fill_fragment(acc[i][j], 0.0f);

    for (int it = 0; it < KIT; it++) {
        // issue next stage
        if (it + 1 < KIT) {
            int k0 = (it + 1) << 5;
            int st = (it + 1) & 1;
#pragma unroll
            for (int a = 0; a < 4; a++) {
                const __nv_bfloat16* base = srcs[a];
                int row0 = (a < 2) ? m0 : n0;
#pragma unroll
                for (int c = 0; c < 2; c++) {
                    uint32_t d = sb_u + st * STAGE_BYTES + a * ARR_BYTES +
                                 (rbase[c] * GTILE + cbase[c]) * 2;
                    cp_async16(d, base + (size_t)(row0 + rbase[c]) * K + k0 + cbase[c]);
                }
            }
            cp_commit();
            cp_wait<1>();   // current stage (it) complete
        } else {
            cp_wait<0>();
        }
        __syncthreads();

        // compute on stage it&1
        char* st = sb + (it & 1) * STAGE_BYTES;
        const __nv_bfloat16* sAh = (const __nv_bfloat16*)(st);
        const __nv_bfloat16* sAl = (const __nv_bfloat16*)(st + ARR_BYTES);
        const __nv_bfloat16* sBh = (const __nv_bfloat16*)(st + 2 * ARR_BYTES);
        const __nv_bfloat16* sBl = (const __nv_bfloat16*)(st + 3 * ARR_BYTES);

#pragma unroll
        for (int ks = 0; ks < 32; ks += 16) {
            wmma::fragment<wmma::matrix_a, 16, 16, 16, __nv_bfloat16, wmma::row_major> fa_h[4], fa_l[4];
            wmma::fragment<wmma::matrix_b, 16, 16, 16, __nv_bfloat16, wmma::col_major> fb_h[2], fb_l[2];
#pragma unroll
            for (int i = 0; i < 4; i++) {
                int r = wm * 64 + i * 16;
                wmma::load_matrix_sync(fa_h[i], sAh + r * GTILE + ks, GTILE);
                wmma::load_matrix_sync(fa_l[i], sAl + r * GTILE + ks, GTILE);
            }
#pragma unroll
            for (int j = 0; j < 2; j++) {
                int r = wn * 32 + j * 16;
                wmma::load_matrix_sync(fb_h[j], sBh + r * GTILE + ks, GTILE);
                wmma::load_matrix_sync(fb_l[j], sBl + r * GTILE + ks, GTILE);
            }
#pragma unroll
            for (int i = 0; i < 4; i++)
#pragma unroll
                for (int j = 0; j < 2; j++) {
                    wmma::mma_sync(acc[i][j], fa_h[i], fb_h[j], acc[i][j]);
                    wmma::mma_sync(acc[i][j], fa_h[i], fb_l[j], acc[i][j]);
                    wmma::mma_sync(acc[i][j], fa_l[i], fb_h[j], acc[i][j]);
                }
        }
        __syncthreads();   // compute done before buffer it&1 is re-issued at it+1
    }

    // epilogue: direct fp32 store
#pragma unroll
    for (int i = 0; i < 4; i++) {
        int row = m0 + wm * 64 + i * 16;
#pragma unroll
        for (int j = 0; j < 2; j++) {
            int col = n0 + wn * 32 + j * 16;
            wmma::store_matrix_sync(C + (size_t)row * N + col, acc[i][j], N, wmma::mem_row_major);
        }
    }
}

// ================= flash attention (causal), fp32 =================
#define QT_S 68
#define PS   65
#define FLASH_SMEM ((2 * 128 * QT_S + 64 * 128 + 64 * PS) * sizeof(float))

__global__ __launch_bounds__(256) void flash_kernel(const float* __restrict__ qkv,
                                                    float* __restrict__ out) {
    extern __shared__ float sm[];
    float* qT = sm;
    float* kT = qT + 128 * QT_S;
    float* vs = kT + 128 * QT_S;
    float* ps = vs + 64 * 128;

    int qb = blockIdx.x;
    int bh = blockIdx.y;
    int b = bh >> 4, h = bh & 15;

    const float* qbase = qkv + (size_t)b * T * K3 + h * HDIM;
    const float* kbase = qbase + INNER;
    const float* vbase = qbase + 2 * INNER;

    int tid = threadIdx.x;
    int ty = tid >> 4, tx = tid & 15;
    int r0 = ty * 4, c0 = tx * 4, d0 = tx * 8;
    const float scale = 0.088388347648318447f;

#pragma unroll
    for (int it = 0; it < 8; it++) {
        int idx = tid + it * 256;
        int r = idx >> 5;
        int dq = (idx & 31) * 4;
        float4 q4 = *(const float4*)(qbase + (size_t)(qb * 64 + r) * K3 + dq);
        qT[(dq + 0) * QT_S + r] = q4.x * scale;
        qT[(dq + 1) * QT_S + r] = q4.y * scale;
        qT[(dq + 2) * QT_S + r] = q4.z * scale;
        qT[(dq + 3) * QT_S + r] = q4.w * scale;
    }

    float m[4], l[4], acc[4][8];
#pragma unroll
    for (int i = 0; i < 4; i++) {
        m[i] = -1e30f; l[i] = 0.f;
#pragma unroll
        for (int j = 0; j < 8; j++) acc[i][j] = 0.f;
    }

    for (int kb = 0; kb <= qb; kb++) {
        __syncthreads();
#pragma unroll
        for (int it = 0; it < 8; it++) {
            int idx = tid + it * 256;
            int r = idx >> 5;
            int dq = (idx & 31) * 4;
            float4 k4 = *(const float4*)(kbase + (size_t)(kb * 64 + r) * K3 + dq);
            kT[(dq + 0) * QT_S + r] = k4.x;
            kT[(dq + 1) * QT_S + r] = k4.y;
            kT[(dq + 2) * QT_S + r] = k4.z;
            kT[(dq + 3) * QT_S + r] = k4.w;
            float4 v4 = *(const float4*)(vbase + (size_t)(kb * 64 + r) * K3 + dq);
            *(float4*)(vs + r * 128 + dq) = v4;
        }
        __syncthreads();

        float s[4][4];
#pragma unroll
        for (int i = 0; i < 4; i++)
#pragma unroll
            for (int j = 0; j < 4; j++) s[i][j] = 0.f;
#pragma unroll 4
        for (int d = 0; d < 128; d++) {
            float4 qv = *(const float4*)(qT + d * QT_S + r0);
            float4 kv = *(const float4*)(kT + d * QT_S + c0);
            float qa[4] = {qv.x, qv.y, qv.z, qv.w};
            float ka[4] = {kv.x, kv.y, kv.z, kv.w};
#pragma unroll
            for (int i = 0; i < 4; i++)
#pragma unroll
                for (int j = 0; j < 4; j++) s[i][j] = fmaf(qa[i], ka[j], s[i][j]);
        }

        if (kb == qb) {
#pragma unroll
            for (int i = 0; i < 4; i++)
#pragma unroll
                for (int j = 0; j < 4; j++)
                    if (c0 + j > r0 + i) s[i][j] = -1e30f;
        }

#pragma unroll
        for (int i = 0; i < 4; i++) {
            float mx = fmaxf(fmaxf(s[i][0], s[i][1]), fmaxf(s[i][2], s[i][3]));
#pragma unroll
            for (int off = 8; off >= 1; off >>= 1)
                mx = fmaxf(mx, __shfl_xor_sync(0xffffffffu, mx, off, 16));
            float mn = fmaxf(m[i], mx);
            float alpha = expf(m[i] - mn);
            m[i] = mn;
            float psum = 0.f;
#pragma unroll
            for (int j = 0; j < 4; j++) {
                float p = expf(s[i][j] - mn);
                ps[(r0 + i) * PS + c0 + j] = p;
                psum += p;
            }
#pragma unroll
            for (int off = 8; off >= 1; off >>= 1)
                psum += __shfl_xor_sync(0xffffffffu, psum, off, 16);
            l[i] = l[i] * alpha + psum;
#pragma unroll
            for (int k = 0; k < 8; k++) acc[i][k] *= alpha;
        }
        __syncthreads();

#pragma unroll 2
        for (int j = 0; j < 64; j++) {
            float4 v0 = *(const float4*)(vs + j * 128 + d0);
            float4 v1 = *(const float4*)(vs + j * 128 + d0 + 4);
#pragma unroll
            for (int i = 0; i < 4; i++) {
                float p = ps[(r0 + i) * PS + j];
                acc[i][0] = fmaf(p, v0.x, acc[i][0]);
                acc[i][1] = fmaf(p, v0.y, acc[i][1]);
                acc[i][2] = fmaf(p, v0.z, acc[i][2]);
                acc[i][3] = fmaf(p, v0.w, acc[i][3]);
                acc[i][4] = fmaf(p, v1.x, acc[i][4]);
                acc[i][5] = fmaf(p, v1.y, acc[i][5]);
                acc[i][6] = fmaf(p, v1.z, acc[i][6]);
                acc[i][7] = fmaf(p, v1.w, acc[i][7]);
            }
        }
    }

#pragma unroll
    for (int i = 0; i < 4; i++) {
        float inv = 1.f / l[i];
        int t = qb * 64 + r0 + i;
        float* op = out + (size_t)(b * T + t) * INNER + h * HDIM + d0;
        *(float4*)op = make_float4(acc[i][0] * inv, acc[i][1] * inv, acc[i][2] * inv, acc[i][3] * inv);
        *(float4*)(op + 4) = make_float4(acc[i][4] * inv, acc[i][5] * inv, acc[i][6] * inv, acc[i][7] * inv);
    }
}

// ================= launch =================
extern "C" void kernel_launch(void* const* d_in, const int* in_sizes, int n_in,
                              void* d_out, int out_size) {
    const float* x     = (const float*)d_in[0];   // [2,2048,2048]
    const float* w_qkv = (const float*)d_in[1];   // [2048,6144]
    const float* w_out = (const float*)d_in[2];   // [2048,2048]
    float* out = (float*)d_out;                   // [2,2048,2048]

    float* qkv;  cudaGetSymbolAddress((void**)&qkv, g_qkv);
    float* attn; cudaGetSymbolAddress((void**)&attn, g_attn);
    __nv_bfloat16 *x_hi, *x_lo, *wqkvT_hi, *wqkvT_lo, *woutT_hi, *woutT_lo, *attn_hi, *attn_lo;
    cudaGetSymbolAddress((void**)&x_hi, g_x_hi);
    cudaGetSymbolAddress((void**)&x_lo, g_x_lo);
    cudaGetSymbolAddress((void**)&wqkvT_hi, g_wqkvT_hi);
    cudaGetSymbolAddress((void**)&wqkvT_lo, g_wqkvT_lo);
    cudaGetSymbolAddress((void**)&woutT_hi, g_woutT_hi);
    cudaGetSymbolAddress((void**)&woutT_lo, g_woutT_lo);
    cudaGetSymbolAddress((void**)&attn_hi, g_attn_hi);
    cudaGetSymbolAddress((void**)&attn_lo, g_attn_lo);

    cudaFuncSetAttribute(flash_kernel, cudaFuncAttributeMaxDynamicSharedMemorySize, (int)FLASH_SMEM);
    cudaFuncSetAttribute(gemm_bf16split, cudaFuncAttributeMaxDynamicSharedMemorySize, GEMM_SMEM);

    // 1. rope tables
    build_rope_tables<<<(T * 64 + 255) / 256, 256>>>();

    // 2. prepack: split x; transpose+split weights
    split_rows_kernel<<<(BT * DIM / 4 + 255) / 256, 256>>>(x, x_hi, x_lo, BT * DIM / 4);
    {
        dim3 blk(32, 8);
        split_transpose_kernel<<<dim3(K3 / 32, DIM / 32), blk>>>(w_qkv, wqkvT_hi, wqkvT_lo, DIM, K3);
        split_transpose_kernel<<<dim3(INNER / 32, DIM / 32), blk>>>(w_out, woutT_hi, woutT_lo, INNER, DIM);
    }

    // 3. QKV projection on tensor cores: [4096,6144] = [4096,2048] @ [2048,6144]
    gemm_bf16split<<<dim3(K3 / 128, BT / 128), 256, GEMM_SMEM>>>(
        BT, K3, DIM, x_hi, x_lo, wqkvT_hi, wqkvT_lo, qkv);

    // 4. RoPE in-place on q,k
    rope_kernel<<<(BT * NHEAD * 64 + 255) / 256, 256>>>(qkv);

    // 5. causal flash attention (fp32)
    flash_kernel<<<dim3(T / 64, BATCH * NHEAD), 256, FLASH_SMEM>>>(qkv, attn);

    // 6. split attention output, then output projection on tensor cores
    split_rows_kernel<<<(BT * INNER / 4 + 255) / 256, 256>>>(attn, attn_hi, attn_lo, BT * INNER / 4);
    gemm_bf16split<<<dim3(INNER / 128, BT / 128), 256, GEMM_SMEM>>>(
        BT, INNER, INNER, attn_hi, attn_lo, woutT_hi, woutT_lo, out);
}